// round 15
// baseline (speedup 1.0000x reference)
#include <cuda_runtime.h>
#include <math.h>
#include <cstdint>

// Problem constants (fixed shapes)
#define BB 2
#define SS 2048
#define DD 1024
#define HH 16
#define DKV 64   // DK == DV == 64

// ---------------------------------------------------------------------------
// Scratch (static __device__ arrays; no allocation allowed)
// ---------------------------------------------------------------------------
__device__ float g_Q[BB * HH * SS * DKV];   // [B,H,S,DK]
__device__ float g_K[BB * HH * SS * DKV];
__device__ float g_V[BB * HH * SS * DKV];
__device__ float g_O[BB * SS * HH * DKV];   // [B,S,H*DV] (concat-heads layout)

// ---------------------------------------------------------------------------
// tf32 helpers (cvt.rna.tf32.f32 is sm_80+ baseline PTX — compiles at
// compute_103; tcgen05 does NOT, per R2 ptxas errors)
// ---------------------------------------------------------------------------
__device__ __forceinline__ uint32_t to_tf32(float x) {
    uint32_t r;
    asm("cvt.rna.tf32.f32 %0, %1;" : "=r"(r) : "f"(x));
    return r;
}
__device__ __forceinline__ float tf32_clean(float x) {
    return __uint_as_float(to_tf32(x));
}

// ---------------------------------------------------------------------------
// Projection GEMM on mma.sync.m16n8k8 tf32 (legacy HMMA path, non-'a' PTX).
// Block tile M=128 x N=64, 256 threads = 8 warps (4 m-warps x 2 n-warps),
// warp tile 32x32 = 2x4 mma tiles. K chunked by 32 (4 ksteps of 8).
//
// MODE 0 (QKV projection): blockIdx.y = head h.
//   C[((b*H+h)*S+s)*64 + n] = tf32_clean( sum_d A[m,d]*W[h,d,n] + bias[h,n] )
//   (tf32-clean store: flash's FFMA then sees exactly-representable values,
//    avoiding a second rounding in any later tf32 stage)
// MODE 1 (output projection): blockIdx.y = 64-col group of Wo.
//   C[m*1024 + n] = sum_d A[m,d]*Wo[d,n] + bias[n]   (plain fp32 store)
//
// Smem padding chosen for conflict-free fragment loads:
//   As stride 36 floats: A-frag bank = (4*gq + tg) mod 32 -> all distinct
//   Bs stride 72 floats: B-frag bank = (8*tg + gq) mod 32 -> all distinct
// ---------------------------------------------------------------------------
template <int MODE>
__global__ __launch_bounds__(256) void proj_mma(
    const float* __restrict__ A, const float* __restrict__ W,
    const float* __restrict__ bias, float* __restrict__ C)
{
    __shared__ uint32_t As[128][36];
    __shared__ uint32_t Bs[32][72];

    const int tid  = threadIdx.x;
    const int lane = tid & 31;
    const int wid  = tid >> 5;
    const int wm   = wid & 3;        // m-warp 0..3
    const int wn   = wid >> 2;       // n-warp 0..1
    const int gq   = lane >> 2;      // group id 0..7
    const int tg   = lane & 3;       // thread-in-group 0..3
    const int m0   = blockIdx.x * 128;

    float acc[2][4][4] = {};

    for (int kt = 0; kt < DD / 32; kt++) {
        const int k0 = kt * 32;

        // --- A tile: 128x32, tf32-rounded, padded stride 36 ---
#pragma unroll
        for (int t = 0; t < 4; t++) {
            const int id = tid + t * 256;          // 0..1023 float4s
            const int r  = id >> 3;
            const int c4 = (id & 7) << 2;
            float4 v = *(const float4*)(A + (size_t)(m0 + r) * DD + k0 + c4);
            uint4 u;
            u.x = to_tf32(v.x); u.y = to_tf32(v.y);
            u.z = to_tf32(v.z); u.w = to_tf32(v.w);
            *(uint4*)&As[r][c4] = u;
        }
        // --- B tile: 32x64 (B[k][n]), tf32-rounded, padded stride 72 ---
#pragma unroll
        for (int t = 0; t < 2; t++) {
            const int id = tid + t * 256;          // 0..511 float4s
            const int kk = id >> 4;
            const int n4 = (id & 15) << 2;
            const float* src = (MODE == 0)
                ? W + ((size_t)blockIdx.y * DD + (k0 + kk)) * DKV + n4
                : W + (size_t)(k0 + kk) * DD + blockIdx.y * 64 + n4;
            float4 v = *(const float4*)src;
            uint4 u;
            u.x = to_tf32(v.x); u.y = to_tf32(v.y);
            u.z = to_tf32(v.z); u.w = to_tf32(v.w);
            *(uint4*)&Bs[kk][n4] = u;
        }
        __syncthreads();

#pragma unroll
        for (int kk = 0; kk < 4; kk++) {
            uint32_t a[2][4], b[4][2];
#pragma unroll
            for (int mt = 0; mt < 2; mt++) {
                const int r = wm * 32 + mt * 16 + gq;
                const int c = kk * 8 + tg;
                a[mt][0] = As[r][c];     a[mt][1] = As[r + 8][c];
                a[mt][2] = As[r][c + 4]; a[mt][3] = As[r + 8][c + 4];
            }
#pragma unroll
            for (int nt = 0; nt < 4; nt++) {
                const int n = wn * 32 + nt * 8 + gq;
                b[nt][0] = Bs[kk * 8 + tg][n];
                b[nt][1] = Bs[kk * 8 + tg + 4][n];
            }
#pragma unroll
            for (int mt = 0; mt < 2; mt++)
#pragma unroll
                for (int nt = 0; nt < 4; nt++) {
                    asm volatile(
                        "mma.sync.aligned.m16n8k8.row.col.f32.tf32.tf32.f32 "
                        "{%0,%1,%2,%3}, {%4,%5,%6,%7}, {%8,%9}, {%0,%1,%2,%3};"
                        : "+f"(acc[mt][nt][0]), "+f"(acc[mt][nt][1]),
                          "+f"(acc[mt][nt][2]), "+f"(acc[mt][nt][3])
                        : "r"(a[mt][0]), "r"(a[mt][1]), "r"(a[mt][2]), "r"(a[mt][3]),
                          "r"(b[nt][0]), "r"(b[nt][1]));
                }
        }
        __syncthreads();
    }

    // --- Epilogue: bias + store (float2, cols 2*tg,2*tg+1 are adjacent) ---
#pragma unroll
    for (int mt = 0; mt < 2; mt++)
#pragma unroll
        for (int half = 0; half < 2; half++) {
            const int m = m0 + wm * 32 + mt * 16 + gq + half * 8;
#pragma unroll
            for (int nt = 0; nt < 4; nt++) {
                const int cl = wn * 32 + nt * 8 + 2 * tg;  // local col 0..63
                const float v0 = acc[mt][nt][half * 2 + 0];
                const float v1 = acc[mt][nt][half * 2 + 1];
                float2 o;
                if (MODE == 0) {
                    const int h = blockIdx.y;
                    o.x = tf32_clean(v0 + bias[h * DKV + cl]);
                    o.y = tf32_clean(v1 + bias[h * DKV + cl + 1]);
                    const int b = m >> 11, s = m & 2047;
                    *(float2*)&C[(((size_t)(b * HH + h)) * SS + s) * DKV + cl] = o;
                } else {
                    const int n = blockIdx.y * 64 + cl;
                    o.x = v0 + bias[n];
                    o.y = v1 + bias[n + 1];
                    *(float2*)&C[(size_t)m * DD + n] = o;
                }
            }
        }
}

// ---------------------------------------------------------------------------
// Flash attention (byte-identical to R1 proven kernel): grid (S/128, B*H).
// ---------------------------------------------------------------------------
#define LDQ 65
__global__ __launch_bounds__(256) void flash_kernel(const float* __restrict__ mask)
{
    extern __shared__ float sm[];
    float* Qs = sm;                      // 128 x 65 (pre-scaled by 1/sqrt(DK))
    float* Ks = Qs + 128 * LDQ;          // 64 x 65
    float* Vs = Ks + 64 * LDQ;           // 64 x 65
    float* Ps = Vs + 64 * LDQ;           // 128 x 65

    const int tid = threadIdx.x;
    const int tx = tid & 15;
    const int ty = tid >> 4;
    const int s0 = blockIdx.x * 128;
    const int bh = blockIdx.y;           // b*H + h
    const int bb = bh >> 4;
    const int hh = bh & 15;

    const float* Qg = g_Q + (size_t)bh * SS * DKV;
    const float* Kg = g_K + (size_t)bh * SS * DKV;
    const float* Vg = g_V + (size_t)bh * SS * DKV;

    for (int i = tid; i < 128 * 64; i += 256) {
        const int r = i >> 6, d = i & 63;
        Qs[r * LDQ + d] = Qg[(size_t)(s0 + r) * DKV + d] * 0.125f;
    }

    float acc[8][4];
    float mrow[8], lrow[8];
#pragma unroll
    for (int r = 0; r < 8; r++) {
        mrow[r] = -INFINITY;
        lrow[r] = 0.f;
#pragma unroll
        for (int c = 0; c < 4; c++) acc[r][c] = 0.f;
    }

    for (int kt = 0; kt < SS / 64; kt++) {
        const int kbase = kt * 64;
        for (int i = tid; i < 64 * 64; i += 256) {
            const int r = i >> 6, d = i & 63;
            Ks[r * LDQ + d] = Kg[(size_t)(kbase + r) * DKV + d];
            Vs[r * LDQ + d] = Vg[(size_t)(kbase + r) * DKV + d];
        }
        __syncthreads();

        float sc[8][4];
#pragma unroll
        for (int r = 0; r < 8; r++)
#pragma unroll
            for (int c = 0; c < 4; c++) sc[r][c] = 0.f;

#pragma unroll 4
        for (int d = 0; d < 64; d++) {
            float a[8], bK[4];
#pragma unroll
            for (int r = 0; r < 8; r++) a[r] = Qs[(ty * 8 + r) * LDQ + d];
#pragma unroll
            for (int c = 0; c < 4; c++) bK[c] = Ks[(tx * 4 + c) * LDQ + d];
#pragma unroll
            for (int r = 0; r < 8; r++)
#pragma unroll
                for (int c = 0; c < 4; c++)
                    sc[r][c] = fmaf(a[r], bK[c], sc[r][c]);
        }

#pragma unroll
        for (int r = 0; r < 8; r++) {
            const int row = ty * 8 + r;
            const float* mp = mask + (size_t)(s0 + row) * SS + kbase + tx * 4;
            float tmax = -INFINITY;
#pragma unroll
            for (int c = 0; c < 4; c++) {
                sc[r][c] += mp[c];
                tmax = fmaxf(tmax, sc[r][c]);
            }
#pragma unroll
            for (int o = 8; o >= 1; o >>= 1)
                tmax = fmaxf(tmax, __shfl_xor_sync(0xffffffffu, tmax, o));
            const float nm = fmaxf(mrow[r], tmax);
            const float corr = __expf(mrow[r] - nm);
            mrow[r] = nm;
            float ps = 0.f;
#pragma unroll
            for (int c = 0; c < 4; c++) {
                const float p = __expf(sc[r][c] - nm);
                Ps[row * LDQ + tx * 4 + c] = p;
                ps += p;
            }
#pragma unroll
            for (int o = 8; o >= 1; o >>= 1)
                ps += __shfl_xor_sync(0xffffffffu, ps, o);
            lrow[r] = lrow[r] * corr + ps;
#pragma unroll
            for (int c = 0; c < 4; c++) acc[r][c] *= corr;
        }
        __syncthreads();

#pragma unroll 4
        for (int kk = 0; kk < 64; kk++) {
            float p8[8], bV[4];
#pragma unroll
            for (int r = 0; r < 8; r++) p8[r] = Ps[(ty * 8 + r) * LDQ + kk];
#pragma unroll
            for (int c = 0; c < 4; c++) bV[c] = Vs[kk * LDQ + tx * 4 + c];
#pragma unroll
            for (int r = 0; r < 8; r++)
#pragma unroll
                for (int c = 0; c < 4; c++)
                    acc[r][c] = fmaf(p8[r], bV[c], acc[r][c]);
        }
        __syncthreads();
    }

#pragma unroll
    for (int r = 0; r < 8; r++) {
        const int row = ty * 8 + r;
        const float inv = 1.f / lrow[r];
#pragma unroll
        for (int c = 0; c < 4; c++) {
            g_O[((size_t)bb * SS + s0 + row) * (HH * DKV) + hh * DKV + tx * 4 + c] =
                acc[r][c] * inv;
        }
    }
}

// ---------------------------------------------------------------------------
// Launch
// ---------------------------------------------------------------------------
extern "C" void kernel_launch(void* const* d_in, const int* in_sizes, int n_in,
                              void* d_out, int out_size)
{
    const float* q    = (const float*)d_in[0];
    const float* k    = (const float*)d_in[1];
    const float* v    = (const float*)d_in[2];
    const float* mask = (const float*)d_in[3];
    const float* Wq   = (const float*)d_in[4];
    const float* bq   = (const float*)d_in[5];
    const float* Wk   = (const float*)d_in[6];
    const float* bk   = (const float*)d_in[7];
    const float* Wv   = (const float*)d_in[8];
    const float* bv   = (const float*)d_in[9];
    const float* Wo   = (const float*)d_in[10];
    const float* bo   = (const float*)d_in[11];
    float* out = (float*)d_out;

    float *gq, *gk, *gv, *go;
    cudaGetSymbolAddress((void**)&gq, g_Q);
    cudaGetSymbolAddress((void**)&gk, g_K);
    cudaGetSymbolAddress((void**)&gv, g_V);
    cudaGetSymbolAddress((void**)&go, g_O);

    // QKV projections on mma.sync tf32 (tf32-clean outputs)
    dim3 gridP(BB * SS / 128, HH);      // (32, 16)
    proj_mma<0><<<gridP, 256>>>(q, Wq, bq, gq);
    proj_mma<0><<<gridP, 256>>>(k, Wk, bk, gk);
    proj_mma<0><<<gridP, 256>>>(v, Wv, bv, gv);

    // Flash attention (fp32 SIMT, unchanged / proven)
    const int smemF = (128 * LDQ + 64 * LDQ + 64 * LDQ + 128 * LDQ) * (int)sizeof(float);
    cudaFuncSetAttribute(flash_kernel, cudaFuncAttributeMaxDynamicSharedMemorySize, smemF);
    flash_kernel<<<dim3(16, 32), 256, smemF>>>(mask);

    // Output projection on mma.sync tf32
    proj_mma<1><<<dim3(BB * SS / 128, DD / 64), 256>>>(go, Wo, bo, out);
}

// round 16
// speedup vs baseline: 1.0053x; 1.0053x over previous
#include <cuda_runtime.h>
#include <math.h>
#include <cstdint>

// Problem constants (fixed shapes)
#define BB 2
#define SS 2048
#define DD 1024
#define HH 16
#define DKV 64   // DK == DV == 64

// ---------------------------------------------------------------------------
// Scratch (static __device__ arrays; no allocation allowed)
// ---------------------------------------------------------------------------
__device__ float g_Q[BB * HH * SS * DKV];   // [B,H,S,DK]
__device__ float g_K[BB * HH * SS * DKV];
__device__ float g_V[BB * HH * SS * DKV];
__device__ float g_O[BB * SS * HH * DKV];   // [B,S,H*DV] (concat-heads layout)

// ---------------------------------------------------------------------------
// tf32 helpers (cvt.rna.tf32.f32 is sm_80+ baseline PTX — compiles at
// compute_103; tcgen05 does NOT, per R2 ptxas errors)
// ---------------------------------------------------------------------------
__device__ __forceinline__ uint32_t to_tf32(float x) {
    uint32_t r;
    asm("cvt.rna.tf32.f32 %0, %1;" : "=r"(r) : "f"(x));
    return r;
}
__device__ __forceinline__ float tf32_clean(float x) {
    return __uint_as_float(to_tf32(x));
}

// ---------------------------------------------------------------------------
// Projection GEMM on mma.sync.m16n8k8 tf32 (legacy HMMA path, non-'a' PTX).
// Block tile M=128 x N=64, 256 threads = 8 warps (4 m-warps x 2 n-warps),
// warp tile 32x32 = 2x4 mma tiles. K chunked by 32 (4 ksteps of 8).
//
// MODE 0 (QKV projection): blockIdx.y = head h.
//   C[((b*H+h)*S+s)*64 + n] = tf32_clean( sum_d A[m,d]*W[h,d,n] + bias[h,n] )
//   (tf32-clean store: flash's FFMA then sees exactly-representable values,
//    avoiding a second rounding in any later tf32 stage)
// MODE 1 (output projection): blockIdx.y = 64-col group of Wo.
//   C[m*1024 + n] = sum_d A[m,d]*Wo[d,n] + bias[n]   (plain fp32 store)
//
// Smem padding chosen for conflict-free fragment loads:
//   As stride 36 floats: A-frag bank = (4*gq + tg) mod 32 -> all distinct
//   Bs stride 72 floats: B-frag bank = (8*tg + gq) mod 32 -> all distinct
// ---------------------------------------------------------------------------
template <int MODE>
__global__ __launch_bounds__(256) void proj_mma(
    const float* __restrict__ A, const float* __restrict__ W,
    const float* __restrict__ bias, float* __restrict__ C)
{
    __shared__ uint32_t As[128][36];
    __shared__ uint32_t Bs[32][72];

    const int tid  = threadIdx.x;
    const int lane = tid & 31;
    const int wid  = tid >> 5;
    const int wm   = wid & 3;        // m-warp 0..3
    const int wn   = wid >> 2;       // n-warp 0..1
    const int gq   = lane >> 2;      // group id 0..7
    const int tg   = lane & 3;       // thread-in-group 0..3
    const int m0   = blockIdx.x * 128;

    float acc[2][4][4] = {};

    for (int kt = 0; kt < DD / 32; kt++) {
        const int k0 = kt * 32;

        // --- A tile: 128x32, tf32-rounded, padded stride 36 ---
#pragma unroll
        for (int t = 0; t < 4; t++) {
            const int id = tid + t * 256;          // 0..1023 float4s
            const int r  = id >> 3;
            const int c4 = (id & 7) << 2;
            float4 v = *(const float4*)(A + (size_t)(m0 + r) * DD + k0 + c4);
            uint4 u;
            u.x = to_tf32(v.x); u.y = to_tf32(v.y);
            u.z = to_tf32(v.z); u.w = to_tf32(v.w);
            *(uint4*)&As[r][c4] = u;
        }
        // --- B tile: 32x64 (B[k][n]), tf32-rounded, padded stride 72 ---
#pragma unroll
        for (int t = 0; t < 2; t++) {
            const int id = tid + t * 256;          // 0..511 float4s
            const int kk = id >> 4;
            const int n4 = (id & 15) << 2;
            const float* src = (MODE == 0)
                ? W + ((size_t)blockIdx.y * DD + (k0 + kk)) * DKV + n4
                : W + (size_t)(k0 + kk) * DD + blockIdx.y * 64 + n4;
            float4 v = *(const float4*)src;
            uint4 u;
            u.x = to_tf32(v.x); u.y = to_tf32(v.y);
            u.z = to_tf32(v.z); u.w = to_tf32(v.w);
            *(uint4*)&Bs[kk][n4] = u;
        }
        __syncthreads();

#pragma unroll
        for (int kk = 0; kk < 4; kk++) {
            uint32_t a[2][4], b[4][2];
#pragma unroll
            for (int mt = 0; mt < 2; mt++) {
                const int r = wm * 32 + mt * 16 + gq;
                const int c = kk * 8 + tg;
                a[mt][0] = As[r][c];     a[mt][1] = As[r + 8][c];
                a[mt][2] = As[r][c + 4]; a[mt][3] = As[r + 8][c + 4];
            }
#pragma unroll
            for (int nt = 0; nt < 4; nt++) {
                const int n = wn * 32 + nt * 8 + gq;
                b[nt][0] = Bs[kk * 8 + tg][n];
                b[nt][1] = Bs[kk * 8 + tg + 4][n];
            }
#pragma unroll
            for (int mt = 0; mt < 2; mt++)
#pragma unroll
                for (int nt = 0; nt < 4; nt++) {
                    asm volatile(
                        "mma.sync.aligned.m16n8k8.row.col.f32.tf32.tf32.f32 "
                        "{%0,%1,%2,%3}, {%4,%5,%6,%7}, {%8,%9}, {%0,%1,%2,%3};"
                        : "+f"(acc[mt][nt][0]), "+f"(acc[mt][nt][1]),
                          "+f"(acc[mt][nt][2]), "+f"(acc[mt][nt][3])
                        : "r"(a[mt][0]), "r"(a[mt][1]), "r"(a[mt][2]), "r"(a[mt][3]),
                          "r"(b[nt][0]), "r"(b[nt][1]));
                }
        }
        __syncthreads();
    }

    // --- Epilogue: bias + store (float2, cols 2*tg,2*tg+1 are adjacent) ---
#pragma unroll
    for (int mt = 0; mt < 2; mt++)
#pragma unroll
        for (int half = 0; half < 2; half++) {
            const int m = m0 + wm * 32 + mt * 16 + gq + half * 8;
#pragma unroll
            for (int nt = 0; nt < 4; nt++) {
                const int cl = wn * 32 + nt * 8 + 2 * tg;  // local col 0..63
                const float v0 = acc[mt][nt][half * 2 + 0];
                const float v1 = acc[mt][nt][half * 2 + 1];
                float2 o;
                if (MODE == 0) {
                    const int h = blockIdx.y;
                    o.x = tf32_clean(v0 + bias[h * DKV + cl]);
                    o.y = tf32_clean(v1 + bias[h * DKV + cl + 1]);
                    const int b = m >> 11, s = m & 2047;
                    *(float2*)&C[(((size_t)(b * HH + h)) * SS + s) * DKV + cl] = o;
                } else {
                    const int n = blockIdx.y * 64 + cl;
                    o.x = v0 + bias[n];
                    o.y = v1 + bias[n + 1];
                    *(float2*)&C[(size_t)m * DD + n] = o;
                }
            }
        }
}

// ---------------------------------------------------------------------------
// Flash attention (byte-identical to R1 proven kernel): grid (S/128, B*H).
// ---------------------------------------------------------------------------
#define LDQ 65
__global__ __launch_bounds__(256) void flash_kernel(const float* __restrict__ mask)
{
    extern __shared__ float sm[];
    float* Qs = sm;                      // 128 x 65 (pre-scaled by 1/sqrt(DK))
    float* Ks = Qs + 128 * LDQ;          // 64 x 65
    float* Vs = Ks + 64 * LDQ;           // 64 x 65
    float* Ps = Vs + 64 * LDQ;           // 128 x 65

    const int tid = threadIdx.x;
    const int tx = tid & 15;
    const int ty = tid >> 4;
    const int s0 = blockIdx.x * 128;
    const int bh = blockIdx.y;           // b*H + h
    const int bb = bh >> 4;
    const int hh = bh & 15;

    const float* Qg = g_Q + (size_t)bh * SS * DKV;
    const float* Kg = g_K + (size_t)bh * SS * DKV;
    const float* Vg = g_V + (size_t)bh * SS * DKV;

    for (int i = tid; i < 128 * 64; i += 256) {
        const int r = i >> 6, d = i & 63;
        Qs[r * LDQ + d] = Qg[(size_t)(s0 + r) * DKV + d] * 0.125f;
    }

    float acc[8][4];
    float mrow[8], lrow[8];
#pragma unroll
    for (int r = 0; r < 8; r++) {
        mrow[r] = -INFINITY;
        lrow[r] = 0.f;
#pragma unroll
        for (int c = 0; c < 4; c++) acc[r][c] = 0.f;
    }

    for (int kt = 0; kt < SS / 64; kt++) {
        const int kbase = kt * 64;
        for (int i = tid; i < 64 * 64; i += 256) {
            const int r = i >> 6, d = i & 63;
            Ks[r * LDQ + d] = Kg[(size_t)(kbase + r) * DKV + d];
            Vs[r * LDQ + d] = Vg[(size_t)(kbase + r) * DKV + d];
        }
        __syncthreads();

        float sc[8][4];
#pragma unroll
        for (int r = 0; r < 8; r++)
#pragma unroll
            for (int c = 0; c < 4; c++) sc[r][c] = 0.f;

#pragma unroll 4
        for (int d = 0; d < 64; d++) {
            float a[8], bK[4];
#pragma unroll
            for (int r = 0; r < 8; r++) a[r] = Qs[(ty * 8 + r) * LDQ + d];
#pragma unroll
            for (int c = 0; c < 4; c++) bK[c] = Ks[(tx * 4 + c) * LDQ + d];
#pragma unroll
            for (int r = 0; r < 8; r++)
#pragma unroll
                for (int c = 0; c < 4; c++)
                    sc[r][c] = fmaf(a[r], bK[c], sc[r][c]);
        }

#pragma unroll
        for (int r = 0; r < 8; r++) {
            const int row = ty * 8 + r;
            const float* mp = mask + (size_t)(s0 + row) * SS + kbase + tx * 4;
            float tmax = -INFINITY;
#pragma unroll
            for (int c = 0; c < 4; c++) {
                sc[r][c] += mp[c];
                tmax = fmaxf(tmax, sc[r][c]);
            }
#pragma unroll
            for (int o = 8; o >= 1; o >>= 1)
                tmax = fmaxf(tmax, __shfl_xor_sync(0xffffffffu, tmax, o));
            const float nm = fmaxf(mrow[r], tmax);
            const float corr = __expf(mrow[r] - nm);
            mrow[r] = nm;
            float ps = 0.f;
#pragma unroll
            for (int c = 0; c < 4; c++) {
                const float p = __expf(sc[r][c] - nm);
                Ps[row * LDQ + tx * 4 + c] = p;
                ps += p;
            }
#pragma unroll
            for (int o = 8; o >= 1; o >>= 1)
                ps += __shfl_xor_sync(0xffffffffu, ps, o);
            lrow[r] = lrow[r] * corr + ps;
#pragma unroll
            for (int c = 0; c < 4; c++) acc[r][c] *= corr;
        }
        __syncthreads();

#pragma unroll 4
        for (int kk = 0; kk < 64; kk++) {
            float p8[8], bV[4];
#pragma unroll
            for (int r = 0; r < 8; r++) p8[r] = Ps[(ty * 8 + r) * LDQ + kk];
#pragma unroll
            for (int c = 0; c < 4; c++) bV[c] = Vs[kk * LDQ + tx * 4 + c];
#pragma unroll
            for (int r = 0; r < 8; r++)
#pragma unroll
                for (int c = 0; c < 4; c++)
                    acc[r][c] = fmaf(p8[r], bV[c], acc[r][c]);
        }
        __syncthreads();
    }

#pragma unroll
    for (int r = 0; r < 8; r++) {
        const int row = ty * 8 + r;
        const float inv = 1.f / lrow[r];
#pragma unroll
        for (int c = 0; c < 4; c++) {
            g_O[((size_t)bb * SS + s0 + row) * (HH * DKV) + hh * DKV + tx * 4 + c] =
                acc[r][c] * inv;
        }
    }
}

// ---------------------------------------------------------------------------
// Launch
// ---------------------------------------------------------------------------
extern "C" void kernel_launch(void* const* d_in, const int* in_sizes, int n_in,
                              void* d_out, int out_size)
{
    const float* q    = (const float*)d_in[0];
    const float* k    = (const float*)d_in[1];
    const float* v    = (const float*)d_in[2];
    const float* mask = (const float*)d_in[3];
    const float* Wq   = (const float*)d_in[4];
    const float* bq   = (const float*)d_in[5];
    const float* Wk   = (const float*)d_in[6];
    const float* bk   = (const float*)d_in[7];
    const float* Wv   = (const float*)d_in[8];
    const float* bv   = (const float*)d_in[9];
    const float* Wo   = (const float*)d_in[10];
    const float* bo   = (const float*)d_in[11];
    float* out = (float*)d_out;

    float *gq, *gk, *gv, *go;
    cudaGetSymbolAddress((void**)&gq, g_Q);
    cudaGetSymbolAddress((void**)&gk, g_K);
    cudaGetSymbolAddress((void**)&gv, g_V);
    cudaGetSymbolAddress((void**)&go, g_O);

    // QKV projections on mma.sync tf32 (tf32-clean outputs)
    dim3 gridP(BB * SS / 128, HH);      // (32, 16)
    proj_mma<0><<<gridP, 256>>>(q, Wq, bq, gq);
    proj_mma<0><<<gridP, 256>>>(k, Wk, bk, gk);
    proj_mma<0><<<gridP, 256>>>(v, Wv, bv, gv);

    // Flash attention (fp32 SIMT, unchanged / proven)
    const int smemF = (128 * LDQ + 64 * LDQ + 64 * LDQ + 128 * LDQ) * (int)sizeof(float);
    cudaFuncSetAttribute(flash_kernel, cudaFuncAttributeMaxDynamicSharedMemorySize, smemF);
    flash_kernel<<<dim3(16, 32), 256, smemF>>>(mask);

    // Output projection on mma.sync tf32
    proj_mma<1><<<dim3(BB * SS / 128, DD / 64), 256>>>(go, Wo, bo, out);
}